// round 13
// baseline (speedup 1.0000x reference)
#include <cuda_runtime.h>

#define PN 4
#define LN 512
#define DN 64

#define L2E  1.4426950408889634f
#define LN2  0.6931471805599453f

// ---------------- device scratch (zero-init; winner resets after use) -------
__device__ __align__(16) float g_rs[PN * LN];   // row sum of exp2(v2)
__device__ __align__(16) float g_cs[PN * LN];   // col sum of exp2(v2)
__device__ float g_pn[PN], g_pd[PN];
__device__ volatile unsigned g_bar0;
__device__ unsigned g_tick;

// ============ single persistent kernel: 128 blocks, 512 thr, 64j x 128k ======
// Min-identity, log2 domain: v2 = (2*sum_d min(a,b) - SA_j - SB_k) * log2e,
// E = exp2(v2).  Row/col/final sums accumulate via REDG atomics (no partial
// arrays, no post-barrier gathers).  c_val rescaled by ln2 once at the end.
__global__ __launch_bounds__(512, 1) void k_all(const float* __restrict__ z,
                                                const float* __restrict__ wgt,
                                                const float* __restrict__ bias,
                                                float* __restrict__ out) {
    extern __shared__ float smd[];
    float* z0s = smd;                 // [64 d][68]  z0 tile, natural
    float* z1s = smd + 64 * 68;       // [64 d][132] z1 tile, natural
    __shared__ float part0[16][65];   // z0 d-quad row sums
    __shared__ float part1[16][129];  // z1 d-quad row sums
    __shared__ float sSA[64], sSB[128];   // pre-scaled by log2e
    __shared__ float scs[16][128];
    __shared__ float sAi[64], sBi[128];
    __shared__ float sn[16], sd[16];
    __shared__ int   s_win;

    const int kb = blockIdx.x, jb = blockIdx.y, p = blockIdx.z;
    const int t  = threadIdx.x;
    const int j0 = jb * 64, k0 = kb * 128;
    const int tx = t & 31, ty = t >> 5;         // lane, warp (= d-quad in prologue)

    const float4* z0g = (const float4*)(z + ((size_t)p * LN + j0) * DN);
    const float4* z1g = (const float4*)(z + ((size_t)(p + PN) * LN + k0) * DN);

    // ---- prologue: batched LDG, then STS + d-quad row-sum partials ----
    float4 v0[2], v1[4];
    #pragma unroll
    for (int i = 0; i < 2; i++) v0[i] = z0g[(tx + 32 * i) * 16 + ty];
    #pragma unroll
    for (int i = 0; i < 4; i++) v1[i] = z1g[(tx + 32 * i) * 16 + ty];

    #pragma unroll
    for (int i = 0; i < 2; i++) {
        int r = tx + 32 * i;                    // j row
        z0s[(4 * ty + 0) * 68 + r] = v0[i].x;
        z0s[(4 * ty + 1) * 68 + r] = v0[i].y;
        z0s[(4 * ty + 2) * 68 + r] = v0[i].z;
        z0s[(4 * ty + 3) * 68 + r] = v0[i].w;
        part0[ty][r] = (v0[i].x + v0[i].y) + (v0[i].z + v0[i].w);
    }
    #pragma unroll
    for (int i = 0; i < 4; i++) {
        int r = tx + 32 * i;                    // k row
        z1s[(4 * ty + 0) * 132 + r] = v1[i].x;
        z1s[(4 * ty + 1) * 132 + r] = v1[i].y;
        z1s[(4 * ty + 2) * 132 + r] = v1[i].z;
        z1s[(4 * ty + 3) * 132 + r] = v1[i].w;
        part1[ty][r] = (v1[i].x + v1[i].y) + (v1[i].z + v1[i].w);
    }
    __syncthreads();

    // SA_j / SB_k (full d sums, pre-scaled by log2e)
    if (t < 64) {
        float s0 = 0.f;
        #pragma unroll
        for (int q = 0; q < 16; q++) s0 += part0[q][t];
        sSA[t] = s0 * L2E;
    } else if (t < 192) {
        int id = t - 64;
        float s1 = 0.f;
        #pragma unroll
        for (int q = 0; q < 16; q++) s1 += part1[q][id];
        sSB[id] = s1 * L2E;
    }

    // ---- mainloop: j = 4*ty..+3, k = 4*tx..+3; acc = sum_d min(a,b) ----
    float acc[4][4];
    #pragma unroll
    for (int jj = 0; jj < 4; jj++)
        #pragma unroll
        for (int i = 0; i < 4; i++) acc[jj][i] = 0.f;

    #pragma unroll 8
    for (int d = 0; d < DN; d++) {
        float4 av = *(const float4*)(z0s + d * 68 + 4 * ty);    // warp-broadcast
        float4 bv = *(const float4*)(z1s + d * 132 + 4 * tx);   // conflict-free
        const float a[4] = { av.x, av.y, av.z, av.w };
        const float b[4] = { bv.x, bv.y, bv.z, bv.w };
        #pragma unroll
        for (int jj = 0; jj < 4; jj++)
            #pragma unroll
            for (int i = 0; i < 4; i++)
                acc[jj][i] += fminf(a[jj], b[i]);   // FMNMX(alu) + FADD(fma)
    }
    __syncthreads();   // sSA/sSB written pre-mainloop by threads 0..191

    // ---- epilogue: v2 = s*log2e via one FMA;  E = exp2(v2) ----
    float v2[4][4], E[4][4];
    {
        float4 SAv = *(const float4*)&sSA[4 * ty];
        float4 SBv = *(const float4*)&sSB[4 * tx];
        const float SAj[4] = { SAv.x, SAv.y, SAv.z, SAv.w };
        const float SBk[4] = { SBv.x, SBv.y, SBv.z, SBv.w };
        #pragma unroll
        for (int jj = 0; jj < 4; jj++)
            #pragma unroll
            for (int i = 0; i < 4; i++) {
                float v = fmaf(2.0f * L2E, acc[jj][i], -(SAj[jj] + SBk[i]));
                v2[jj][i] = v;
                E[jj][i]  = exp2f(v);
            }
    }

    // ---- row sums (full: this block's 128 k + REDG across 4 kb) ----
    #pragma unroll
    for (int jj = 0; jj < 4; jj++) {
        float e = (E[jj][0] + E[jj][1]) + (E[jj][2] + E[jj][3]);
        #pragma unroll
        for (int o = 16; o; o >>= 1) e += __shfl_xor_sync(~0u, e, o);
        if (tx == 0)
            atomicAdd(&g_rs[p * LN + j0 + 4 * ty + jj], e);
    }

    // ---- col sums (block-local 64 j, then REDG across 8 jb) ----
    {
        float c0 = 0, c1 = 0, c2 = 0, c3 = 0;
        #pragma unroll
        for (int jj = 0; jj < 4; jj++) {
            c0 += E[jj][0]; c1 += E[jj][1]; c2 += E[jj][2]; c3 += E[jj][3];
        }
        *(float4*)&scs[ty][4 * tx] = make_float4(c0, c1, c2, c3);
    }
    __syncthreads();
    if (t < 128) {
        float e = 0.f;
        #pragma unroll
        for (int q = 0; q < 16; q++) e += scs[q][t];
        atomicAdd(&g_cs[p * LN + k0 + t], e);
    }

    // ---- grid barrier (128 co-resident blocks) ----
    __threadfence();
    __syncthreads();
    if (t == 0) {
        atomicAdd((unsigned*)&g_bar0, 1u);
        while (g_bar0 < 128u) { }
    }
    __syncthreads();

    // ---- 1/rowsum, 1/colsum (single coalesced L2 load each) ----
    if (t < 64) {
        sAi[t] = 1.0f / __ldcg(&g_rs[p * LN + j0 + t]);
    } else if (t < 192) {
        int id = t - 64;
        sBi[id] = 1.0f / __ldcg(&g_cs[p * LN + k0 + id]);
    }
    __syncthreads();

    // ---- phase C: own-tile sum(c*v2), sum(c) ----
    {
        float4 Bv = *(const float4*)&sBi[4 * tx];
        const float Bk[4] = { Bv.x, Bv.y, Bv.z, Bv.w };
        float num = 0.f, den = 0.f;
        #pragma unroll
        for (int jj = 0; jj < 4; jj++) {
            float Aj = sAi[4 * ty + jj];         // broadcast
            #pragma unroll
            for (int i = 0; i < 4; i++) {
                float a = E[jj][i] * Aj;
                float b = E[jj][i] * Bk[i];
                float c = a + b - a * b;
                num = fmaf(c, v2[jj][i], num);
                den += c;
            }
        }
        #pragma unroll
        for (int o = 16; o; o >>= 1) {
            num += __shfl_xor_sync(~0u, num, o);
            den += __shfl_xor_sync(~0u, den, o);
        }
        if (tx == 0) { sn[ty] = num; sd[ty] = den; }
        __syncthreads();
        if (t == 0) {
            float N = 0.f, D = 0.f;
            #pragma unroll
            for (int q = 0; q < 16; q++) { N += sn[q]; D += sd[q]; }
            atomicAdd(&g_pn[p], N);
            atomicAdd(&g_pd[p], D);
        }
    }

    // ---- ticket: last block finalizes + resets ----
    __threadfence();
    __syncthreads();
    if (t == 0) s_win = (atomicAdd(&g_tick, 1u) == 127u) ? 1 : 0;
    __syncthreads();
    if (!s_win) return;

    if (t < 16) {
        int pp = t >> 2;
        float cv = (__ldcg(&g_pn[pp]) / __ldcg(&g_pd[pp])) * LN2;
        out[t] = cv * wgt[t & 3] + bias[t & 3];
    }
    __syncthreads();                             // reads done before resets
    #pragma unroll
    for (int i = 0; i < 4; i++) {                // reset accumulators for replay
        g_rs[i * 512 + t] = 0.f;
        g_cs[i * 512 + t] = 0.f;
    }
    if (t < PN) { g_pn[t] = 0.f; g_pd[t] = 0.f; }
    if (t == 0) { g_bar0 = 0; g_tick = 0; }
}

// ---------------- launch ----------------
extern "C" void kernel_launch(void* const* d_in, const int* in_sizes, int n_in,
                              void* d_out, int out_size) {
    const float* z = (const float*)d_in[0];   // (8, 512, 64) fp32
    const float* w = (const float*)d_in[1];   // (1, 4)
    const float* b = (const float*)d_in[2];   // (4,)
    float* out = (float*)d_out;               // (4, 4)

    const int smem = (68 + 132) * 64 * 4;     // 51200 B dynamic
    cudaFuncSetAttribute(k_all, cudaFuncAttributeMaxDynamicSharedMemorySize, smem);
    k_all<<<dim3(4, 8, 4), 512, smem>>>(z, w, b, out);
}

// round 14
// speedup vs baseline: 1.1577x; 1.1577x over previous
#include <cuda_runtime.h>
#include <cuda_fp16.h>

#define PN 4
#define LN 512
#define DN 64

#define L2E  1.4426950408889634f
#define LN2  0.6931471805599453f

// ---------------- device scratch (zero-init; winner resets after use) -------
__device__ __align__(16) float g_rs[PN * LN];   // row sum of exp2(v2)
__device__ __align__(16) float g_cs[PN * LN];   // col sum of exp2(v2)
__device__ float g_pn[PN], g_pd[PN];
__device__ volatile unsigned g_bar0;
__device__ unsigned g_tick;

// ============ single persistent kernel: 128 blocks, 512 thr, 64j x 128k ======
// Min-identity in fp16x2: acc = sum_d min(a,b) via HMNMX2 + HADD2 (1 op per
// element for each), fp16 partials spilled to fp32 every 16 d.  Errors are
// softmax-shift-invariant (common-mode) or averaged out over 512 rows.
// s*log2e = 2*L2E*acc - SA_j - SB_k (SA/SB pre-scaled fp32), E = exp2(.).
__global__ __launch_bounds__(512, 1) void k_all(const float* __restrict__ z,
                                                const float* __restrict__ wgt,
                                                const float* __restrict__ bias,
                                                float* __restrict__ out) {
    extern __shared__ char smraw[];
    __half2* z0h = (__half2*)smraw;               // [64 d][68]  dup pairs (aj,aj)
    __half2* z1h = (__half2*)smraw + 64 * 68;     // [64 d][66]  k pairs (b2p,b2p+1)
    __shared__ float part0[16][65];   // z0 d-quad row sums (fp32)
    __shared__ float part1[16][129];  // z1 d-quad row sums (fp32)
    __shared__ float sSA[64], sSB[128];   // pre-scaled by log2e
    __shared__ float scs[16][128];
    __shared__ float sAi[64], sBi[128];
    __shared__ float sn[16], sd[16];
    __shared__ int   s_win;

    const int kb = blockIdx.x, jb = blockIdx.y, p = blockIdx.z;
    const int t  = threadIdx.x;
    const int j0 = jb * 64, k0 = kb * 128;
    const int tx = t & 31, ty = t >> 5;         // lane, warp (= d-quad in prologue)

    const float4* z0g = (const float4*)(z + ((size_t)p * LN + j0) * DN);
    const float4* z1g = (const float4*)(z + ((size_t)(p + PN) * LN + k0) * DN);

    // ---- prologue: z0 -> dup half2 pairs; d-quad row sums (fp32) ----
    #pragma unroll
    for (int i = 0; i < 2; i++) {
        int r = tx + 32 * i;                    // j row 0..63
        float4 v = z0g[r * 16 + ty];
        z0h[(4 * ty + 0) * 68 + r] = __floats2half2_rn(v.x, v.x);
        z0h[(4 * ty + 1) * 68 + r] = __floats2half2_rn(v.y, v.y);
        z0h[(4 * ty + 2) * 68 + r] = __floats2half2_rn(v.z, v.z);
        z0h[(4 * ty + 3) * 68 + r] = __floats2half2_rn(v.w, v.w);
        part0[ty][r] = (v.x + v.y) + (v.z + v.w);
    }
    // ---- prologue: z1 -> k-pair half2 (b_{2p}, b_{2p+1}) ----
    #pragma unroll
    for (int i = 0; i < 2; i++) {
        int pi = tx + 32 * i;                   // k pair 0..63
        float4 ue = z1g[(2 * pi + 0) * 16 + ty];
        float4 uo = z1g[(2 * pi + 1) * 16 + ty];
        z1h[(4 * ty + 0) * 66 + pi] = __floats2half2_rn(ue.x, uo.x);
        z1h[(4 * ty + 1) * 66 + pi] = __floats2half2_rn(ue.y, uo.y);
        z1h[(4 * ty + 2) * 66 + pi] = __floats2half2_rn(ue.z, uo.z);
        z1h[(4 * ty + 3) * 66 + pi] = __floats2half2_rn(ue.w, uo.w);
        part1[ty][2 * pi + 0] = (ue.x + ue.y) + (ue.z + ue.w);
        part1[ty][2 * pi + 1] = (uo.x + uo.y) + (uo.z + uo.w);
    }
    __syncthreads();

    // SA_j / SB_k (full d sums, pre-scaled by log2e)
    if (t < 64) {
        float s0 = 0.f;
        #pragma unroll
        for (int q = 0; q < 16; q++) s0 += part0[q][t];
        sSA[t] = s0 * L2E;
    } else if (t < 192) {
        int id = t - 64;
        float s1 = 0.f;
        #pragma unroll
        for (int q = 0; q < 16; q++) s1 += part1[q][id];
        sSB[id] = s1 * L2E;
    }

    // ---- mainloop: j = 4*ty..+3, k = 4*tx..+3 ----
    // fp16 chunk partials (16 d), spilled to fp32 accf.
    float accf[4][4];
    #pragma unroll
    for (int jj = 0; jj < 4; jj++)
        #pragma unroll
        for (int i = 0; i < 4; i++) accf[jj][i] = 0.f;

    const __half2* z0b = z0h + 4 * ty;           // dup pairs of j-quad
    const __half2* z1b = z1h + 2 * tx;           // k pairs (2 half2 = k-quad)

    #pragma unroll
    for (int ch = 0; ch < 4; ch++) {
        __half2 acch[4][2];
        #pragma unroll
        for (int jj = 0; jj < 4; jj++) {
            acch[jj][0] = __floats2half2_rn(0.f, 0.f);
            acch[jj][1] = __floats2half2_rn(0.f, 0.f);
        }
        #pragma unroll
        for (int dd = 0; dd < 16; dd++) {
            int d = ch * 16 + dd;
            uint4 araw = *(const uint4*)(z0b + d * 68);        // 4 dup half2, bcast
            uint2 braw = *(const uint2*)(z1b + d * 66);        // 2 pair half2
            const __half2* av = (const __half2*)&araw;
            const __half2* bv = (const __half2*)&braw;
            #pragma unroll
            for (int jj = 0; jj < 4; jj++) {
                acch[jj][0] = __hadd2(acch[jj][0], __hmin2(av[jj], bv[0]));
                acch[jj][1] = __hadd2(acch[jj][1], __hmin2(av[jj], bv[1]));
            }
        }
        #pragma unroll
        for (int jj = 0; jj < 4; jj++) {
            float2 f0 = __half22float2(acch[jj][0]);
            float2 f1 = __half22float2(acch[jj][1]);
            accf[jj][0] += f0.x; accf[jj][1] += f0.y;
            accf[jj][2] += f1.x; accf[jj][3] += f1.y;
        }
    }
    __syncthreads();   // sSA/sSB written pre-mainloop by threads 0..191

    // ---- epilogue: v2 = 2*L2E*acc - SA - SB;  E = exp2(v2) ----
    float v2[4][4], E[4][4];
    {
        float4 SAv = *(const float4*)&sSA[4 * ty];
        float4 SBv = *(const float4*)&sSB[4 * tx];
        const float SAj[4] = { SAv.x, SAv.y, SAv.z, SAv.w };
        const float SBk[4] = { SBv.x, SBv.y, SBv.z, SBv.w };
        #pragma unroll
        for (int jj = 0; jj < 4; jj++)
            #pragma unroll
            for (int i = 0; i < 4; i++) {
                float v = fmaf(2.0f * L2E, accf[jj][i], -(SAj[jj] + SBk[i]));
                v2[jj][i] = v;
                E[jj][i]  = exp2f(v);
            }
    }

    // ---- row sums (this block's 128 k, REDG across 4 kb) ----
    #pragma unroll
    for (int jj = 0; jj < 4; jj++) {
        float e = (E[jj][0] + E[jj][1]) + (E[jj][2] + E[jj][3]);
        #pragma unroll
        for (int o = 16; o; o >>= 1) e += __shfl_xor_sync(~0u, e, o);
        if (tx == 0)
            atomicAdd(&g_rs[p * LN + j0 + 4 * ty + jj], e);
    }

    // ---- col sums (block-local 64 j, REDG across 8 jb) ----
    {
        float c0 = 0, c1 = 0, c2 = 0, c3 = 0;
        #pragma unroll
        for (int jj = 0; jj < 4; jj++) {
            c0 += E[jj][0]; c1 += E[jj][1]; c2 += E[jj][2]; c3 += E[jj][3];
        }
        *(float4*)&scs[ty][4 * tx] = make_float4(c0, c1, c2, c3);
    }
    __syncthreads();
    if (t < 128) {
        float e = 0.f;
        #pragma unroll
        for (int q = 0; q < 16; q++) e += scs[q][t];
        atomicAdd(&g_cs[p * LN + k0 + t], e);
    }

    // ---- grid barrier (128 co-resident blocks) ----
    __threadfence();
    __syncthreads();
    if (t == 0) {
        atomicAdd((unsigned*)&g_bar0, 1u);
        while (g_bar0 < 128u) { }
    }
    __syncthreads();

    // ---- 1/rowsum, 1/colsum ----
    if (t < 64) {
        sAi[t] = 1.0f / __ldcg(&g_rs[p * LN + j0 + t]);
    } else if (t < 192) {
        int id = t - 64;
        sBi[id] = 1.0f / __ldcg(&g_cs[p * LN + k0 + id]);
    }
    __syncthreads();

    // ---- phase C: own-tile sum(c*v2), sum(c) ----
    {
        float4 Bv = *(const float4*)&sBi[4 * tx];
        const float Bk[4] = { Bv.x, Bv.y, Bv.z, Bv.w };
        float num = 0.f, den = 0.f;
        #pragma unroll
        for (int jj = 0; jj < 4; jj++) {
            float Aj = sAi[4 * ty + jj];         // broadcast
            #pragma unroll
            for (int i = 0; i < 4; i++) {
                float a = E[jj][i] * Aj;
                float b = E[jj][i] * Bk[i];
                float c = a + b - a * b;
                num = fmaf(c, v2[jj][i], num);
                den += c;
            }
        }
        #pragma unroll
        for (int o = 16; o; o >>= 1) {
            num += __shfl_xor_sync(~0u, num, o);
            den += __shfl_xor_sync(~0u, den, o);
        }
        if (tx == 0) { sn[ty] = num; sd[ty] = den; }
        __syncthreads();
        if (t == 0) {
            float N = 0.f, D = 0.f;
            #pragma unroll
            for (int q = 0; q < 16; q++) { N += sn[q]; D += sd[q]; }
            atomicAdd(&g_pn[p], N);
            atomicAdd(&g_pd[p], D);
        }
    }

    // ---- ticket: last block finalizes + resets ----
    __threadfence();
    __syncthreads();
    if (t == 0) s_win = (atomicAdd(&g_tick, 1u) == 127u) ? 1 : 0;
    __syncthreads();
    if (!s_win) return;

    if (t < 16) {
        int pp = t >> 2;
        float cv = (__ldcg(&g_pn[pp]) / __ldcg(&g_pd[pp])) * LN2;
        out[t] = cv * wgt[t & 3] + bias[t & 3];
    }
    __syncthreads();                             // reads done before resets
    #pragma unroll
    for (int i = 0; i < 4; i++) {                // reset accumulators for replay
        g_rs[i * 512 + t] = 0.f;
        g_cs[i * 512 + t] = 0.f;
    }
    if (t < PN) { g_pn[t] = 0.f; g_pd[t] = 0.f; }
    if (t == 0) { g_bar0 = 0; g_tick = 0; }
}

// ---------------- launch ----------------
extern "C" void kernel_launch(void* const* d_in, const int* in_sizes, int n_in,
                              void* d_out, int out_size) {
    const float* z = (const float*)d_in[0];   // (8, 512, 64) fp32
    const float* w = (const float*)d_in[1];   // (1, 4)
    const float* b = (const float*)d_in[2];   // (4,)
    float* out = (float*)d_out;               // (4, 4)

    const int smem = (68 + 66) * 64 * 4;      // 34304 B dynamic (half2 tiles)
    cudaFuncSetAttribute(k_all, cudaFuncAttributeMaxDynamicSharedMemorySize, smem);
    k_all<<<dim3(4, 8, 4), 512, smem>>>(z, w, b, out);
}